// round 3
// baseline (speedup 1.0000x reference)
#include <cuda_runtime.h>
#include <math.h>

#define Bn 32
#define Qn 2000
#define Gn 64
#define Cn 80

// Scratch: cost/iou stored g-major per image for coalesced column scans in stage B.
__device__ float g_costT[Bn * Gn * Qn];   // [b][g][q]
__device__ float g_iouT [Bn * Gn * Qn];   // [b][g][q]
__device__ int   g_gmin [Bn * Qn];        // first argmin over g of cost row (pen-invariant dedup target)

// ---------------------------------------------------------------------------
// Stage A: pairwise cost + iou + row argmin
// ---------------------------------------------------------------------------
__global__ void stageA(const float* __restrict__ logits,   // [B,Q,C]
                       const float* __restrict__ boxes,    // [B,Q,4]
                       const int*   __restrict__ gtcls,    // [B,G]
                       const float* __restrict__ gtbox,    // [B,G,4]
                       const float* __restrict__ szout,    // [B,4]
                       const float* __restrict__ sztgt)    // [B,G,4]
{
    int b = blockIdx.x;
    int q = blockIdx.y * blockDim.x + threadIdx.x;

    __shared__ float sg[Gn * 4];
    __shared__ float st[Gn * 4];
    __shared__ int   sc[Gn];
    for (int i = threadIdx.x; i < Gn * 4; i += blockDim.x) {
        sg[i] = gtbox[b * Gn * 4 + i];
        st[i] = sztgt[b * Gn * 4 + i];
    }
    for (int i = threadIdx.x; i < Gn; i += blockDim.x) sc[i] = gtcls[b * Gn + i];
    __syncthreads();
    if (q >= Qn) return;

    const float* bp = boxes + (size_t)(b * Qn + q) * 4;
    float x1 = bp[0], y1 = bp[1], x2 = bp[2], y2 = bp[3];
    float cx = (x1 + x2) * 0.5f, cy = (y1 + y2) * 0.5f;
    float areaA = (x2 - x1) * (y2 - y1);

    // fg mask: any(in_boxes) | any(in_centers)
    bool anyIB = false, anyIC = false;
    for (int g = 0; g < Gn; g++) {
        float gx1 = sg[g * 4], gy1 = sg[g * 4 + 1], gx2 = sg[g * 4 + 2], gy2 = sg[g * 4 + 3];
        bool ib = (cx > gx1) && (cx < gx2) && (cy > gy1) && (cy < gy2);
        float gcx = (gx1 + gx2) * 0.5f, gcy = (gy1 + gy2) * 0.5f;
        float gw = gx2 - gx1, gh = gy2 - gy1;
        bool ic = (cx > gcx - 2.5f * gw) && (cx < gcx + 2.5f * gw) &&
                  (cy > gcy - 2.5f * gh) && (cy < gcy + 2.5f * gh);
        anyIB |= ib; anyIC |= ic;
    }
    float fgpen = (anyIB || anyIC) ? 0.f : 1e4f;

    float so0 = szout[b * 4], so1 = szout[b * 4 + 1], so2 = szout[b * 4 + 2], so3 = szout[b * 4 + 3];
    float nx1 = x1 / so0, ny1 = y1 / so1, nx2 = x2 / so2, ny2 = y2 / so3;
    const float* lr = logits + (size_t)(b * Qn + q) * Cn;

    float* costOut = g_costT + (size_t)b * Gn * Qn;
    float* iouOut  = g_iouT  + (size_t)b * Gn * Qn;

    float best = 3.4e38f; int bidx = 0;
    for (int g = 0; g < Gn; g++) {
        float gx1 = sg[g * 4], gy1 = sg[g * 4 + 1], gx2 = sg[g * 4 + 2], gy2 = sg[g * 4 + 3];
        float areaB = (gx2 - gx1) * (gy2 - gy1);
        float ix1 = fmaxf(x1, gx1), iy1 = fmaxf(y1, gy1);
        float ix2 = fminf(x2, gx2), iy2 = fminf(y2, gy2);
        float iw = fmaxf(ix2 - ix1, 0.f), ih = fmaxf(iy2 - iy1, 0.f);
        float inter = iw * ih;
        float uni = areaA + areaB - inter;
        float iou = inter / uni;
        float ex1 = fminf(x1, gx1), ey1 = fminf(y1, gy1);
        float ex2 = fmaxf(x2, gx2), ey2 = fmaxf(y2, gy2);
        float ew = fmaxf(ex2 - ex1, 0.f), eh = fmaxf(ey2 - ey1, 0.f);
        float areaC = ew * eh;
        float giou = iou - (areaC - uni) / areaC;

        bool ib = (cx > gx1) && (cx < gx2) && (cy > gy1) && (cy < gy2);
        float gcx = (gx1 + gx2) * 0.5f, gcy = (gy1 + gy2) * 0.5f;
        float gw = gx2 - gx1, gh = gy2 - gy1;
        bool ic = (cx > gcx - 2.5f * gw) && (cx < gcx + 2.5f * gw) &&
                  (cy > gcy - 2.5f * gh) && (cy < gcy + 2.5f * gh);
        bool inbc = ib && ic;

        float p = lr[sc[g]];
        float pos = 0.25f * (1.f - p) * (1.f - p) * (-logf(p + 1e-8f));
        float neg = 0.75f * p * p * (-logf(1.f - p + 1e-8f));
        float ccost = pos - neg;

        float t0 = st[g * 4], t1 = st[g * 4 + 1], t2 = st[g * 4 + 2], t3 = st[g * 4 + 3];
        float cb = fabsf(nx1 - gx1 / t0) + fabsf(ny1 - gy1 / t1) +
                   fabsf(nx2 - gx2 / t2) + fabsf(ny2 - gy2 / t3);

        float cost = 5.f * cb + 2.f * ccost + 2.f * (-giou) + (inbc ? 0.f : 100.f) + fgpen;
        costOut[(size_t)g * Qn + q] = cost;
        iouOut [(size_t)g * Qn + q] = iou;
        if (cost < best) { best = cost; bidx = g; }   // first-occurrence min
    }
    g_gmin[b * Qn + q] = bidx;
}

// ---------------------------------------------------------------------------
// Stage B: one block per image; dynamic-k init + bounded refinement loop
// ---------------------------------------------------------------------------
__device__ __forceinline__ void warpArgMin(float& v, int& i) {
    for (int off = 16; off; off >>= 1) {
        float ov = __shfl_down_sync(0xffffffffu, v, off);
        int   oi = __shfl_down_sync(0xffffffffu, i, off);
        if (ov < v || (ov == v && oi < i)) { v = ov; i = oi; }
    }
    v = __shfl_sync(0xffffffffu, v, 0);
    i = __shfl_sync(0xffffffffu, i, 0);
}
__device__ __forceinline__ void warpArgMax(float& v, int& i) {
    for (int off = 16; off; off >>= 1) {
        float ov = __shfl_down_sync(0xffffffffu, v, off);
        int   oi = __shfl_down_sync(0xffffffffu, i, off);
        if (ov > v || (ov == v && oi < i)) { v = ov; i = oi; }
    }
    v = __shfl_sync(0xffffffffu, v, 0);
    i = __shfl_sync(0xffffffffu, i, 0);
}

__global__ __launch_bounds__(512) void stageB(float* __restrict__ out)
{
    int b = blockIdx.x;
    int tid = threadIdx.x, lane = tid & 31, wid = tid >> 5;   // 16 warps, 4 gts each

    __shared__ float              s_pen[Qn];
    __shared__ unsigned long long s_match[Qn];
    __shared__ unsigned long long s_or;

    const float* costB = g_costT + (size_t)b * Gn * Qn;
    const float* iouB  = g_iouT  + (size_t)b * Gn * Qn;
    const int*   gminB = g_gmin  + b * Qn;

    for (int q = tid; q < Qn; q += 512) { s_pen[q] = 0.f; s_match[q] = 0ull; }
    __syncthreads();

    // ---- initial dynamic-k matching: one warp per 4 gts ----
    for (int j = 0; j < 4; j++) {
        int g = (wid << 2) + j;
        const float* ic = iouB + (size_t)g * Qn;
        int chosen[5];
        float sum = 0.f;
        // top-5 ious (descending), summed in that order (== jax top_k order)
        for (int pass = 0; pass < 5; pass++) {
            float bv = -1.f; int bi = 0x7fffffff;
            for (int q = lane; q < Qn; q += 32) {
                bool ex = false;
                #pragma unroll
                for (int c = 0; c < 5; c++) if (c < pass && chosen[c] == q) ex = true;
                if (ex) continue;
                float v = ic[q];
                if (v > bv || (v == bv && q < bi)) { bv = v; bi = q; }
            }
            warpArgMax(bv, bi);
            chosen[pass] = bi;
            sum += bv;
        }
        int k = (int)sum;              // truncating cast, as in the reference
        if (k < 1) k = 1;
        if (k > 5) k = 5;              // sum of 5 ious <= 5, clamp is a no-op safeguard
        // k smallest costs, stable (value,index) order == argsort(argsort) rank < k
        const float* cc = costB + (size_t)g * Qn;
        for (int pass = 0; pass < k; pass++) {
            float bv = 3.4e38f; int bi = 0x7fffffff;
            for (int q = lane; q < Qn; q += 32) {
                bool ex = false;
                #pragma unroll
                for (int c = 0; c < 5; c++) if (c < pass && chosen[c] == q) ex = true;
                if (ex) continue;
                float v = cc[q];
                if (v < bv || (v == bv && q < bi)) { bv = v; bi = q; }
            }
            warpArgMin(bv, bi);
            chosen[pass] = bi;
            if (lane == 0) atomicOr(&s_match[bi], 1ull << g);
        }
    }
    __syncthreads();

    // ---- dedup (row penalty is row-constant => keep-gt == precomputed gmin) ----
    for (int q = tid; q < Qn; q += 512) {
        unsigned long long m = s_match[q];
        if (__popcll(m) > 1) s_match[q] = 1ull << gminB[q];
    }
    __syncthreads();

    // ---- bounded force-match loop (early break == frozen no-op iterations) ----
    for (int iter = 0; iter < Gn; iter++) {
        if (tid == 0) s_or = 0ull;
        __syncthreads();
        unsigned long long loc = 0ull;
        for (int q = tid; q < Qn; q += 512) loc |= s_match[q];
        for (int off = 16; off; off >>= 1) loc |= __shfl_down_sync(0xffffffffu, loc, off);
        if (lane == 0) atomicOr(&s_or, loc);
        __syncthreads();
        unsigned long long unm = ~s_or;      // all 64 gt slots are valid
        if (unm == 0ull) break;

        // penalize currently-matched rows (accumulates, matching cost mutation)
        for (int q = tid; q < Qn; q += 512)
            if (s_match[q] != 0ull) s_pen[q] += 1e5f;
        __syncthreads();

        // each unmatched gt grabs its argmin-cost query
        for (int j = 0; j < 4; j++) {
            int g = (wid << 2) + j;
            if (!((unm >> g) & 1ull)) continue;
            const float* cc = costB + (size_t)g * Qn;
            float bv = 3.4e38f; int bi = 0x7fffffff;
            for (int q = lane; q < Qn; q += 32) {
                float v = cc[q] + s_pen[q];
                if (v < bv || (v == bv && q < bi)) { bv = v; bi = q; }
            }
            warpArgMin(bv, bi);
            if (lane == 0) atomicOr(&s_match[bi], 1ull << g);
        }
        __syncthreads();

        for (int q = tid; q < Qn; q += 512) {
            unsigned long long m = s_match[q];
            if (__popcll(m) > 1) s_match[q] = 1ull << gminB[q];
        }
        __syncthreads();
    }

    // ---- outputs ----
    // matching matrix [B,Q,G] in 0/1 float
    float* outM = out + (size_t)b * Qn * Gn;
    for (int q = tid; q < Qn; q += 512) {
        unsigned long long m = s_match[q];
        float* row = outM + (size_t)q * Gn;
        for (int g = 0; g < Gn; g++) row[g] = ((m >> g) & 1ull) ? 1.f : 0.f;
    }
    // matched_query_id [B,G]: argmin over matched rows of final (cost+pen), else 0
    float* outI = out + (size_t)Bn * Qn * Gn + (size_t)b * Gn;
    for (int j = 0; j < 4; j++) {
        int g = (wid << 2) + j;
        const float* cc = costB + (size_t)g * Qn;
        float bv = 3.4e38f; int bi = 0x7fffffff;
        for (int q = lane; q < Qn; q += 32) {
            if ((s_match[q] >> g) & 1ull) {
                float v = cc[q] + s_pen[q];
                if (v < bv || (v == bv && q < bi)) { bv = v; bi = q; }
            }
        }
        warpArgMin(bv, bi);
        if (lane == 0) outI[g] = (bi == 0x7fffffff) ? 0.f : (float)bi;
    }
}

// ---------------------------------------------------------------------------
extern "C" void kernel_launch(void* const* d_in, const int* in_sizes, int n_in,
                              void* d_out, int out_size)
{
    const float* logits = (const float*)d_in[0];   // pred_logits [B,Q,C]
    const float* boxes  = (const float*)d_in[1];   // pred_boxes  [B,Q,4]
    const int*   gtc    = (const int*)  d_in[2];   // gt_classes  [B,G]
    const float* gtb    = (const float*)d_in[3];   // gt_boxes    [B,G,4]
    const float* szo    = (const float*)d_in[4];   // image_size_xyxy     [B,4]
    const float* szt    = (const float*)d_in[5];   // image_size_xyxy_tgt [B,G,4]

    dim3 gA(Bn, (Qn + 127) / 128);
    stageA<<<gA, 128>>>(logits, boxes, gtc, gtb, szo, szt);
    stageB<<<Bn, 512>>>((float*)d_out);
}

// round 4
// speedup vs baseline: 3.7195x; 3.7195x over previous
#include <cuda_runtime.h>
#include <math.h>

#define Bn 32
#define Qn 2000
#define Gn 64
#define Cn 80

// Scratch: cost/iou stored g-major per image for coalesced column scans.
__device__ float g_costT[Bn * Gn * Qn];            // [b][g][q]
__device__ float g_iouT [Bn * Gn * Qn];            // [b][g][q]
__device__ int   g_gmin [Bn * Qn];                 // first argmin over g of cost row
__device__ int   g_selq [Bn * Gn * 5];             // initial matched query ids per gt
__device__ int   g_selk [Bn * Gn];                 // dynamic k per gt
__device__ unsigned long long g_match[Bn * Qn];    // final match bitmask per query

// ---------------------------------------------------------------------------
// Stage A: pairwise cost + iou + row argmin
// ---------------------------------------------------------------------------
__global__ void stageA(const float* __restrict__ logits,   // [B,Q,C]
                       const float* __restrict__ boxes,    // [B,Q,4]
                       const int*   __restrict__ gtcls,    // [B,G]
                       const float* __restrict__ gtbox,    // [B,G,4]
                       const float* __restrict__ szout,    // [B,4]
                       const float* __restrict__ sztgt)    // [B,G,4]
{
    int b = blockIdx.x;
    int q = blockIdx.y * blockDim.x + threadIdx.x;

    __shared__ float sg[Gn * 4];
    __shared__ float st[Gn * 4];
    __shared__ int   sc[Gn];
    for (int i = threadIdx.x; i < Gn * 4; i += blockDim.x) {
        sg[i] = gtbox[b * Gn * 4 + i];
        st[i] = sztgt[b * Gn * 4 + i];
    }
    for (int i = threadIdx.x; i < Gn; i += blockDim.x) sc[i] = gtcls[b * Gn + i];
    __syncthreads();
    if (q >= Qn) return;

    const float* bp = boxes + (size_t)(b * Qn + q) * 4;
    float x1 = bp[0], y1 = bp[1], x2 = bp[2], y2 = bp[3];
    float cx = (x1 + x2) * 0.5f, cy = (y1 + y2) * 0.5f;
    float areaA = (x2 - x1) * (y2 - y1);

    bool anyIB = false, anyIC = false;
    for (int g = 0; g < Gn; g++) {
        float gx1 = sg[g * 4], gy1 = sg[g * 4 + 1], gx2 = sg[g * 4 + 2], gy2 = sg[g * 4 + 3];
        bool ib = (cx > gx1) && (cx < gx2) && (cy > gy1) && (cy < gy2);
        float gcx = (gx1 + gx2) * 0.5f, gcy = (gy1 + gy2) * 0.5f;
        float gw = gx2 - gx1, gh = gy2 - gy1;
        bool ic = (cx > gcx - 2.5f * gw) && (cx < gcx + 2.5f * gw) &&
                  (cy > gcy - 2.5f * gh) && (cy < gcy + 2.5f * gh);
        anyIB |= ib; anyIC |= ic;
    }
    float fgpen = (anyIB || anyIC) ? 0.f : 1e4f;

    float so0 = szout[b * 4], so1 = szout[b * 4 + 1], so2 = szout[b * 4 + 2], so3 = szout[b * 4 + 3];
    float nx1 = x1 / so0, ny1 = y1 / so1, nx2 = x2 / so2, ny2 = y2 / so3;
    const float* lr = logits + (size_t)(b * Qn + q) * Cn;

    float* costOut = g_costT + (size_t)b * Gn * Qn;
    float* iouOut  = g_iouT  + (size_t)b * Gn * Qn;

    float best = 3.4e38f; int bidx = 0;
    for (int g = 0; g < Gn; g++) {
        float gx1 = sg[g * 4], gy1 = sg[g * 4 + 1], gx2 = sg[g * 4 + 2], gy2 = sg[g * 4 + 3];
        float areaB = (gx2 - gx1) * (gy2 - gy1);
        float ix1 = fmaxf(x1, gx1), iy1 = fmaxf(y1, gy1);
        float ix2 = fminf(x2, gx2), iy2 = fminf(y2, gy2);
        float iw = fmaxf(ix2 - ix1, 0.f), ih = fmaxf(iy2 - iy1, 0.f);
        float inter = iw * ih;
        float uni = areaA + areaB - inter;
        float iou = inter / uni;
        float ex1 = fminf(x1, gx1), ey1 = fminf(y1, gy1);
        float ex2 = fmaxf(x2, gx2), ey2 = fmaxf(y2, gy2);
        float ew = fmaxf(ex2 - ex1, 0.f), eh = fmaxf(ey2 - ey1, 0.f);
        float areaC = ew * eh;
        float giou = iou - (areaC - uni) / areaC;

        bool ib = (cx > gx1) && (cx < gx2) && (cy > gy1) && (cy < gy2);
        float gcx = (gx1 + gx2) * 0.5f, gcy = (gy1 + gy2) * 0.5f;
        float gw = gx2 - gx1, gh = gy2 - gy1;
        bool ic = (cx > gcx - 2.5f * gw) && (cx < gcx + 2.5f * gw) &&
                  (cy > gcy - 2.5f * gh) && (cy < gcy + 2.5f * gh);
        bool inbc = ib && ic;

        float p = lr[sc[g]];
        float pos = 0.25f * (1.f - p) * (1.f - p) * (-logf(p + 1e-8f));
        float neg = 0.75f * p * p * (-logf(1.f - p + 1e-8f));
        float ccost = pos - neg;

        float t0 = st[g * 4], t1 = st[g * 4 + 1], t2 = st[g * 4 + 2], t3 = st[g * 4 + 3];
        float cb = fabsf(nx1 - gx1 / t0) + fabsf(ny1 - gy1 / t1) +
                   fabsf(nx2 - gx2 / t2) + fabsf(ny2 - gy2 / t3);

        float cost = 5.f * cb + 2.f * ccost + 2.f * (-giou) + (inbc ? 0.f : 100.f) + fgpen;
        costOut[(size_t)g * Qn + q] = cost;
        iouOut [(size_t)g * Qn + q] = iou;
        if (cost < best) { best = cost; bidx = g; }   // first-occurrence min
    }
    g_gmin[b * Qn + q] = bidx;
}

// ---------------------------------------------------------------------------
// Stage Sel: one block per (b,g). Column cached in smem, pass-based selection.
// ---------------------------------------------------------------------------
__device__ __forceinline__ void warpAMax(float& v, int& i) {
    for (int off = 16; off; off >>= 1) {
        float ov = __shfl_down_sync(0xffffffffu, v, off);
        int   oi = __shfl_down_sync(0xffffffffu, i, off);
        if (ov > v || (ov == v && oi < i)) { v = ov; i = oi; }
    }
}
__device__ __forceinline__ void warpAMin(float& v, int& i) {
    for (int off = 16; off; off >>= 1) {
        float ov = __shfl_down_sync(0xffffffffu, v, off);
        int   oi = __shfl_down_sync(0xffffffffu, i, off);
        if (ov < v || (ov == v && oi < i)) { v = ov; i = oi; }
    }
}

__global__ __launch_bounds__(256) void stageSel()
{
    int bg = blockIdx.x;                  // b*Gn + g
    int tid = threadIdx.x, lane = tid & 31, wid = tid >> 5;   // 8 warps

    __shared__ float s_iou[Qn];
    __shared__ float s_cost[Qn];
    __shared__ float s_rv[8];
    __shared__ int   s_ri[8];
    __shared__ float s_bv;
    __shared__ int   s_bi;

    const float* ic = g_iouT  + (size_t)bg * Qn;
    const float* cc = g_costT + (size_t)bg * Qn;
    for (int q = tid; q < Qn; q += 256) { s_iou[q] = ic[q]; s_cost[q] = cc[q]; }
    __syncthreads();

    // top-5 ious, summed in descending order (== jax top_k order)
    float sum = 0.f;
    for (int pass = 0; pass < 5; pass++) {
        float bv = -3.4e38f; int bi = 0x7fffffff;
        for (int q = tid; q < Qn; q += 256) {
            float v = s_iou[q];
            if (v > bv || (v == bv && q < bi)) { bv = v; bi = q; }
        }
        warpAMax(bv, bi);
        if (lane == 0) { s_rv[wid] = bv; s_ri[wid] = bi; }
        __syncthreads();
        if (tid == 0) {
            float fv = s_rv[0]; int fi = s_ri[0];
            for (int w = 1; w < 8; w++)
                if (s_rv[w] > fv || (s_rv[w] == fv && s_ri[w] < fi)) { fv = s_rv[w]; fi = s_ri[w]; }
            s_bv = fv; s_bi = fi;
            s_iou[fi] = -3.4e38f;   // exclude
        }
        __syncthreads();
        sum += s_bv;                // identical on all threads
    }
    int k = (int)sum;               // truncating cast, as in the reference
    if (k < 1) k = 1;
    if (k > 5) k = 5;

    // k smallest costs, first-index tie-break (== argsort(argsort) rank < k)
    for (int pass = 0; pass < k; pass++) {
        float bv = 3.4e38f; int bi = 0x7fffffff;
        for (int q = tid; q < Qn; q += 256) {
            float v = s_cost[q];
            if (v < bv || (v == bv && q < bi)) { bv = v; bi = q; }
        }
        warpAMin(bv, bi);
        if (lane == 0) { s_rv[wid] = bv; s_ri[wid] = bi; }
        __syncthreads();
        if (tid == 0) {
            float fv = s_rv[0]; int fi = s_ri[0];
            for (int w = 1; w < 8; w++)
                if (s_rv[w] < fv || (s_rv[w] == fv && s_ri[w] < fi)) { fv = s_rv[w]; fi = s_ri[w]; }
            s_cost[fi] = 3.4e38f;   // exclude
            g_selq[bg * 5 + pass] = fi;
        }
        __syncthreads();
    }
    if (tid == 0) g_selk[bg] = k;
}

// ---------------------------------------------------------------------------
// Stage B2: one block per image; dedup + bounded refinement loop
// ---------------------------------------------------------------------------
__device__ __forceinline__ void warpArgMinB(float& v, int& i) {
    for (int off = 16; off; off >>= 1) {
        float ov = __shfl_down_sync(0xffffffffu, v, off);
        int   oi = __shfl_down_sync(0xffffffffu, i, off);
        if (ov < v || (ov == v && oi < i)) { v = ov; i = oi; }
    }
    v = __shfl_sync(0xffffffffu, v, 0);
    i = __shfl_sync(0xffffffffu, i, 0);
}

__global__ __launch_bounds__(512) void stageB2(float* __restrict__ out)
{
    int b = blockIdx.x;
    int tid = threadIdx.x, lane = tid & 31, wid = tid >> 5;   // 16 warps, 4 gts each

    __shared__ float              s_pen[Qn];
    __shared__ unsigned long long s_match[Qn];
    __shared__ unsigned long long s_or;

    const float* costB = g_costT + (size_t)b * Gn * Qn;
    const int*   gminB = g_gmin  + b * Qn;

    for (int q = tid; q < Qn; q += 512) { s_pen[q] = 0.f; s_match[q] = 0ull; }
    __syncthreads();

    // build initial match from precomputed per-gt selections
    if (tid < Gn) {
        int bg = b * Gn + tid;
        int k = g_selk[bg];
        for (int p = 0; p < k; p++)
            atomicOr(&s_match[g_selq[bg * 5 + p]], 1ull << tid);
    }
    __syncthreads();

    // dedup (row penalty is row-constant => keep-gt == precomputed gmin)
    for (int q = tid; q < Qn; q += 512) {
        unsigned long long m = s_match[q];
        if (__popcll(m) > 1) s_match[q] = 1ull << gminB[q];
    }
    __syncthreads();

    // bounded force-match loop (early break == frozen no-op iterations)
    for (int iter = 0; iter < Gn; iter++) {
        if (tid == 0) s_or = 0ull;
        __syncthreads();
        unsigned long long loc = 0ull;
        for (int q = tid; q < Qn; q += 512) loc |= s_match[q];
        for (int off = 16; off; off >>= 1) loc |= __shfl_down_sync(0xffffffffu, loc, off);
        if (lane == 0) atomicOr(&s_or, loc);
        __syncthreads();
        unsigned long long unm = ~s_or;
        if (unm == 0ull) break;

        for (int q = tid; q < Qn; q += 512)
            if (s_match[q] != 0ull) s_pen[q] += 1e5f;
        __syncthreads();

        for (int j = 0; j < 4; j++) {
            int g = (wid << 2) + j;
            if (!((unm >> g) & 1ull)) continue;
            const float* cc = costB + (size_t)g * Qn;
            float bv = 3.4e38f; int bi = 0x7fffffff;
            for (int q = lane; q < Qn; q += 32) {
                float v = cc[q] + s_pen[q];
                if (v < bv || (v == bv && q < bi)) { bv = v; bi = q; }
            }
            warpArgMinB(bv, bi);
            if (lane == 0) atomicOr(&s_match[bi], 1ull << g);
        }
        __syncthreads();

        for (int q = tid; q < Qn; q += 512) {
            unsigned long long m = s_match[q];
            if (__popcll(m) > 1) s_match[q] = 1ull << gminB[q];
        }
        __syncthreads();
    }

    // persist match state + write matched_query_id [B,G]
    for (int q = tid; q < Qn; q += 512) g_match[b * Qn + q] = s_match[q];

    float* outI = out + (size_t)Bn * Qn * Gn + (size_t)b * Gn;
    for (int j = 0; j < 4; j++) {
        int g = (wid << 2) + j;
        const float* cc = costB + (size_t)g * Qn;
        float bv = 3.4e38f; int bi = 0x7fffffff;
        for (int q = lane; q < Qn; q += 32) {
            if ((s_match[q] >> g) & 1ull) {
                float v = cc[q] + s_pen[q];
                if (v < bv || (v == bv && q < bi)) { bv = v; bi = q; }
            }
        }
        warpArgMinB(bv, bi);
        if (lane == 0) outI[g] = (bi == 0x7fffffff) ? 0.f : (float)bi;
    }
}

// ---------------------------------------------------------------------------
// Stage Out: expand bitmask to [B,Q,G] float matrix, full-chip coalesced
// ---------------------------------------------------------------------------
__global__ __launch_bounds__(256) void stageOut(float* __restrict__ out)
{
    int b = blockIdx.x;
    int base = blockIdx.y * 256 + threadIdx.x;
    const unsigned long long* mrow = g_match + b * Qn;
    float* orow = out + (size_t)b * Qn * Gn;
    for (int i = base; i < Qn * Gn; i += 16 * 256) {
        int q = i >> 6, g = i & 63;
        orow[i] = ((mrow[q] >> g) & 1ull) ? 1.f : 0.f;
    }
}

// ---------------------------------------------------------------------------
extern "C" void kernel_launch(void* const* d_in, const int* in_sizes, int n_in,
                              void* d_out, int out_size)
{
    const float* logits = (const float*)d_in[0];
    const float* boxes  = (const float*)d_in[1];
    const int*   gtc    = (const int*)  d_in[2];
    const float* gtb    = (const float*)d_in[3];
    const float* szo    = (const float*)d_in[4];
    const float* szt    = (const float*)d_in[5];

    dim3 gA(Bn, (Qn + 127) / 128);
    stageA<<<gA, 128>>>(logits, boxes, gtc, gtb, szo, szt);
    stageSel<<<Bn * Gn, 256>>>();
    stageB2<<<Bn, 512>>>((float*)d_out);
    stageOut<<<dim3(Bn, 16), 256>>>((float*)d_out);
}